// round 2
// baseline (speedup 1.0000x reference)
#include <cuda_runtime.h>
#include <cuda_bf16.h>
#include <stdint.h>
#include <stddef.h>

#define BDIM 64
#define SDIM 512
#define IDIM 1024
#define HDIM 1024
#define GDIM 4096            // 4*H
#define MROWS (BDIM*SDIM)    // 32768

// ---------------- static device scratch (no allocations allowed) ----------------
__device__ float          g_xW [(size_t)MROWS * GDIM];   // 512 MB: x@W + bias
__device__ __nv_bfloat16  g_xhi[(size_t)MROWS * IDIM];
__device__ __nv_bfloat16  g_xlo[(size_t)MROWS * IDIM];
__device__ __nv_bfloat16  g_Whi[(size_t)IDIM * GDIM];
__device__ __nv_bfloat16  g_Wlo[(size_t)IDIM * GDIM];
__device__ __nv_bfloat16  g_Uhi[(size_t)HDIM * GDIM];
__device__ __nv_bfloat16  g_Ulo[(size_t)HDIM * GDIM];
__device__ __nv_bfloat16  g_hbuf[2][2][BDIM * HDIM];     // [parity][hi/lo]
__device__ float          g_c  [BDIM * HDIM];

// ---------------- helpers ----------------
#define MMA_BF16(Cr, Ar, Br)                                                    \
  asm volatile("mma.sync.aligned.m16n8k16.row.col.f32.bf16.bf16.f32 "           \
               "{%0,%1,%2,%3},{%4,%5,%6,%7},{%8,%9},{%0,%1,%2,%3};"             \
               : "+f"(Cr[0]), "+f"(Cr[1]), "+f"(Cr[2]), "+f"(Cr[3])             \
               : "r"(Ar[0]), "r"(Ar[1]), "r"(Ar[2]), "r"(Ar[3]),                \
                 "r"(Br[0]), "r"(Br[1]))

__device__ __forceinline__ float sigm(float x) { return 1.f / (1.f + __expf(-x)); }
__device__ __forceinline__ float tanh_f(float x) {
    float e = __expf(-2.f * fabsf(x));
    float r = (1.f - e) / (1.f + e);
    return (x < 0.f) ? -r : r;
}

// ---------------- prep: fp32 -> bf16 hi/lo split ----------------
__global__ void split_kernel(const float* __restrict__ src, int n, int which) {
    __nv_bfloat16 *hi, *lo;
    if (which == 0)      { hi = g_xhi; lo = g_xlo; }
    else if (which == 1) { hi = g_Whi; lo = g_Wlo; }
    else                 { hi = g_Uhi; lo = g_Ulo; }
    int i = blockIdx.x * blockDim.x + threadIdx.x;
    if (i < n) {
        float v = src[i];
        __nv_bfloat16 h = __float2bfloat16(v);
        hi[i] = h;
        lo[i] = __float2bfloat16(v - __bfloat162float(h));
    }
}

__global__ void zero_state_kernel() {
    int i = blockIdx.x * blockDim.x + threadIdx.x;
    if (i < BDIM * HDIM) {
        __nv_bfloat16 z = __float2bfloat16(0.f);
        g_hbuf[0][0][i] = z; g_hbuf[0][1][i] = z;
        g_hbuf[1][0][i] = z; g_hbuf[1][1][i] = z;
        g_c[i] = 0.f;
    }
}

// ---------------- phase 1: xW = x @ W + bias  (bf16x3 MMA) ----------------
// CTA tile 128x64, 4 warps in 2x2 grid (warp tile 64x32), BK=16, double-buffered.
__global__ __launch_bounds__(128) void gemm_xw_kernel(const float* __restrict__ bias) {
    const int m0 = blockIdx.y * 128;
    const int n0 = blockIdx.x * 64;
    const int tid = threadIdx.x;
    const int warp = tid >> 5, lane = tid & 31;
    const int g = lane >> 2, tig = lane & 3;
    const int wm = warp >> 1, wn = warp & 1;

    __shared__ __align__(16) __nv_bfloat16 As[2][2][128][24];  // [buf][hi/lo][m][k]
    __shared__ __align__(16) __nv_bfloat16 Bs[2][2][64][24];   // [buf][hi/lo][n][k]

    float C[4][4][4];
#pragma unroll
    for (int a = 0; a < 4; a++)
#pragma unroll
        for (int b = 0; b < 4; b++)
#pragma unroll
            for (int c = 0; c < 4; c++) C[a][b][c] = 0.f;

    const int ar = tid >> 2;          // A row  0..31 (+32*it)
    const int ac = (tid & 3) * 4;     // A col  0,4,8,12
    const int bk = tid >> 4;          // B k    0..7 (+8*it)
    const int bc = (tid & 15) * 4;    // B col  0..60

    uint2 regA[2][4];
    uint2 regB[2][2];

    auto gload = [&](int k0) {
#pragma unroll
        for (int it = 0; it < 4; ++it) {
            size_t off = (size_t)(m0 + ar + 32 * it) * IDIM + k0 + ac;
            regA[0][it] = *reinterpret_cast<const uint2*>(g_xhi + off);
            regA[1][it] = *reinterpret_cast<const uint2*>(g_xlo + off);
        }
#pragma unroll
        for (int it = 0; it < 2; ++it) {
            size_t off = (size_t)(k0 + bk + 8 * it) * GDIM + n0 + bc;
            regB[0][it] = *reinterpret_cast<const uint2*>(g_Whi + off);
            regB[1][it] = *reinterpret_cast<const uint2*>(g_Wlo + off);
        }
    };
    auto sts = [&](int buf) {
#pragma unroll
        for (int h = 0; h < 2; ++h)
#pragma unroll
            for (int it = 0; it < 4; ++it)
                *reinterpret_cast<uint2*>(&As[buf][h][ar + 32 * it][ac]) = regA[h][it];
#pragma unroll
        for (int h = 0; h < 2; ++h)
#pragma unroll
            for (int it = 0; it < 2; ++it) {
                __nv_bfloat16 tmp[4];
                *reinterpret_cast<uint2*>(tmp) = regB[h][it];
#pragma unroll
                for (int j = 0; j < 4; ++j) Bs[buf][h][bc + j][bk + 8 * it] = tmp[j];
            }
    };

    gload(0);
    sts(0);
    __syncthreads();

    const int KT = IDIM / 16;
    for (int kt = 0; kt < KT; ++kt) {
        const int cur = kt & 1;
        if (kt + 1 < KT) gload((kt + 1) * 16);

        uint32_t aF[2][4][4];
        uint32_t bF[2][4][2];
#pragma unroll
        for (int mt = 0; mt < 4; ++mt) {
            const int rb = wm * 64 + mt * 16;
#pragma unroll
            for (int h = 0; h < 2; ++h) {
                aF[h][mt][0] = *reinterpret_cast<const uint32_t*>(&As[cur][h][rb + g][2 * tig]);
                aF[h][mt][1] = *reinterpret_cast<const uint32_t*>(&As[cur][h][rb + g + 8][2 * tig]);
                aF[h][mt][2] = *reinterpret_cast<const uint32_t*>(&As[cur][h][rb + g][2 * tig + 8]);
                aF[h][mt][3] = *reinterpret_cast<const uint32_t*>(&As[cur][h][rb + g + 8][2 * tig + 8]);
            }
        }
#pragma unroll
        for (int nt = 0; nt < 4; ++nt) {
            const int nb = wn * 32 + nt * 8;
#pragma unroll
            for (int h = 0; h < 2; ++h) {
                bF[h][nt][0] = *reinterpret_cast<const uint32_t*>(&Bs[cur][h][nb + g][2 * tig]);
                bF[h][nt][1] = *reinterpret_cast<const uint32_t*>(&Bs[cur][h][nb + g][2 * tig + 8]);
            }
        }
#pragma unroll
        for (int mt = 0; mt < 4; ++mt)
#pragma unroll
            for (int nt = 0; nt < 4; ++nt) {
                MMA_BF16(C[mt][nt], aF[0][mt], bF[0][nt]);  // hi*hi
                MMA_BF16(C[mt][nt], aF[0][mt], bF[1][nt]);  // hi*lo
                MMA_BF16(C[mt][nt], aF[1][mt], bF[0][nt]);  // lo*hi
            }

        if (kt + 1 < KT) sts(cur ^ 1);
        __syncthreads();
    }

#pragma unroll
    for (int mt = 0; mt < 4; ++mt) {
        const int row0 = m0 + wm * 64 + mt * 16 + g;
#pragma unroll
        for (int nt = 0; nt < 4; ++nt) {
            const int col = n0 + wn * 32 + nt * 8 + 2 * tig;
            const float b0 = bias[col], b1 = bias[col + 1];
            float2 v;
            v.x = C[mt][nt][0] + b0; v.y = C[mt][nt][1] + b1;
            *reinterpret_cast<float2*>(&g_xW[(size_t)row0 * GDIM + col]) = v;
            v.x = C[mt][nt][2] + b0; v.y = C[mt][nt][3] + b1;
            *reinterpret_cast<float2*>(&g_xW[(size_t)(row0 + 8) * GDIM + col]) = v;
        }
    }
}

// ---------------- phase 2: one recurrent step -------------------------------
// gates = xW[:,t,:] + h @ U  ; fused LSTM cell epilogue.
// 128 CTAs, each owns 8 hidden units j0..j0+7 and computes ALL 4 gate column
// groups for them (cols q*1024 + j0 + jj) -> cell update is register-local.
// h double-buffered (parity of t) to avoid cross-CTA read/write race.
__global__ __launch_bounds__(128) void lstm_step_kernel(float* __restrict__ out, int t,
                                                        float* __restrict__ ht,
                                                        float* __restrict__ ct) {
    const int j0 = blockIdx.x * 8;
    const int tid = threadIdx.x;
    const int warp = tid >> 5, lane = tid & 31;
    const int g = lane >> 2, tig = lane & 3;
    const int p = t & 1, np = p ^ 1;
    const __nv_bfloat16* __restrict__ hhi = g_hbuf[p][0];
    const __nv_bfloat16* __restrict__ hlo = g_hbuf[p][1];

    __shared__ __align__(16) __nv_bfloat16 As[2][2][64][24];   // h tile [m][k]
    __shared__ __align__(16) __nv_bfloat16 Bs[2][2][32][24];   // U tile [n][k]

    // init accumulators from xW (already has bias)
    float C[4][4];
    {
        const int b0 = warp * 16 + g;
#pragma unroll
        for (int nt = 0; nt < 4; ++nt) {
            const int n = nt * 1024 + j0 + 2 * tig;
            float2 v0 = *reinterpret_cast<const float2*>(&g_xW[(size_t)(b0 * SDIM + t) * GDIM + n]);
            float2 v1 = *reinterpret_cast<const float2*>(&g_xW[(size_t)((b0 + 8) * SDIM + t) * GDIM + n]);
            C[nt][0] = v0.x; C[nt][1] = v0.y; C[nt][2] = v1.x; C[nt][3] = v1.y;
        }
    }

    const int ar = tid >> 2;        // 0..31 (+32*it)
    const int ac = (tid & 3) * 4;   // 0,4,8,12
    const int bkk = tid >> 3;       // 0..15
    const int bc = (tid & 7) * 4;   // 0..28
    const int nB = (bc >> 3) * 1024 + j0 + (bc & 7);  // global U column of this 4-vec

    uint2 regA[2][2];
    uint2 regB[2];

    auto gload = [&](int k0) {
#pragma unroll
        for (int it = 0; it < 2; ++it) {
            size_t off = (size_t)(ar + 32 * it) * HDIM + k0 + ac;
            regA[0][it] = *reinterpret_cast<const uint2*>(hhi + off);
            regA[1][it] = *reinterpret_cast<const uint2*>(hlo + off);
        }
        size_t offB = (size_t)(k0 + bkk) * GDIM + nB;
        regB[0] = *reinterpret_cast<const uint2*>(g_Uhi + offB);
        regB[1] = *reinterpret_cast<const uint2*>(g_Ulo + offB);
    };
    auto sts = [&](int buf) {
#pragma unroll
        for (int h = 0; h < 2; ++h)
#pragma unroll
            for (int it = 0; it < 2; ++it)
                *reinterpret_cast<uint2*>(&As[buf][h][ar + 32 * it][ac]) = regA[h][it];
#pragma unroll
        for (int h = 0; h < 2; ++h) {
            __nv_bfloat16 tmp[4];
            *reinterpret_cast<uint2*>(tmp) = regB[h];
#pragma unroll
            for (int j = 0; j < 4; ++j) Bs[buf][h][bc + j][bkk] = tmp[j];
        }
    };

    gload(0);
    sts(0);
    __syncthreads();

    const int KT = HDIM / 16;
    for (int kt = 0; kt < KT; ++kt) {
        const int cur = kt & 1;
        if (kt + 1 < KT) gload((kt + 1) * 16);

        uint32_t aF[2][4];
        uint32_t bF[2][4][2];
        const int rb = warp * 16;
#pragma unroll
        for (int h = 0; h < 2; ++h) {
            aF[h][0] = *reinterpret_cast<const uint32_t*>(&As[cur][h][rb + g][2 * tig]);
            aF[h][1] = *reinterpret_cast<const uint32_t*>(&As[cur][h][rb + g + 8][2 * tig]);
            aF[h][2] = *reinterpret_cast<const uint32_t*>(&As[cur][h][rb + g][2 * tig + 8]);
            aF[h][3] = *reinterpret_cast<const uint32_t*>(&As[cur][h][rb + g + 8][2 * tig + 8]);
        }
#pragma unroll
        for (int nt = 0; nt < 4; ++nt)
#pragma unroll
            for (int h = 0; h < 2; ++h) {
                bF[h][nt][0] = *reinterpret_cast<const uint32_t*>(&Bs[cur][h][nt * 8 + g][2 * tig]);
                bF[h][nt][1] = *reinterpret_cast<const uint32_t*>(&Bs[cur][h][nt * 8 + g][2 * tig + 8]);
            }
#pragma unroll
        for (int nt = 0; nt < 4; ++nt) {
            MMA_BF16(C[nt], aF[0], bF[0][nt]);
            MMA_BF16(C[nt], aF[0], bF[1][nt]);
            MMA_BF16(C[nt], aF[1], bF[0][nt]);
        }

        if (kt + 1 < KT) sts(cur ^ 1);
        __syncthreads();
    }

    // fused LSTM cell epilogue: this thread holds i,f,g,o for 4 (batch,unit) pairs
#pragma unroll
    for (int ci = 0; ci < 4; ++ci) {
        const int b = warp * 16 + g + ((ci & 2) ? 8 : 0);
        const int j = j0 + 2 * tig + (ci & 1);
        const float is = sigm(C[0][ci]);
        const float fs = sigm(C[1][ci]);
        const float gt = tanh_f(C[2][ci]);
        const float os = sigm(C[3][ci]);
        const float cold = g_c[b * HDIM + j];
        const float cnew = fs * cold + is * gt;
        g_c[b * HDIM + j] = cnew;
        const float h = os * tanh_f(cnew);
        out[(size_t)(b * SDIM + t) * HDIM + j] = h;
        __nv_bfloat16 hh = __float2bfloat16(h);
        g_hbuf[np][0][b * HDIM + j] = hh;
        g_hbuf[np][1][b * HDIM + j] = __float2bfloat16(h - __bfloat162float(hh));
        if (ht != nullptr && t == SDIM - 1) {
            ht[b * HDIM + j] = h;
            ct[b * HDIM + j] = cnew;
        }
    }
}

// ---------------- launch ----------------
extern "C" void kernel_launch(void* const* d_in, const int* in_sizes, int n_in,
                              void* d_out, int out_size) {
    const float* x    = (const float*)d_in[0];
    const float* W    = (const float*)d_in[1];
    const float* U    = (const float*)d_in[2];
    const float* bias = (const float*)d_in[3];
    float* out = (float*)d_out;
    (void)in_sizes; (void)n_in;

    {
        int n = MROWS * IDIM;
        split_kernel<<<(n + 255) / 256, 256>>>(x, n, 0);
    }
    {
        int n = IDIM * GDIM;
        split_kernel<<<(n + 255) / 256, 256>>>(W, n, 1);
        split_kernel<<<(n + 255) / 256, 256>>>(U, n, 2);
    }
    zero_state_kernel<<<(BDIM * HDIM + 255) / 256, 256>>>();

    gemm_xw_kernel<<<dim3(GDIM / 64, MROWS / 128), 128>>>(bias);

    float* ht = nullptr;
    float* ct = nullptr;
    long long hs_elems = (long long)BDIM * SDIM * HDIM;
    if ((long long)out_size >= hs_elems + 2LL * BDIM * HDIM) {
        ht = out + hs_elems;
        ct = ht + (long long)BDIM * HDIM;
    }

    for (int t = 0; t < SDIM; ++t)
        lstm_step_kernel<<<128, 128>>>(out, t, ht, ct);
}

// round 3
// speedup vs baseline: 2.3587x; 2.3587x over previous
#include <cuda_runtime.h>
#include <cuda_bf16.h>
#include <stdint.h>
#include <stddef.h>

#define BDIM 64
#define SDIM 512
#define IDIM 1024
#define HDIM 1024
#define GDIM 4096            // 4*H
#define MROWS (BDIM*SDIM)    // 32768
#define NCTA 128

// ---------------- static device scratch (no allocations allowed) ----------------
__device__ float          g_xW [(size_t)MROWS * GDIM];   // 512 MB: x@W + bias
__device__ __nv_bfloat16  g_xhi[(size_t)MROWS * IDIM];
__device__ __nv_bfloat16  g_xlo[(size_t)MROWS * IDIM];
__device__ __nv_bfloat16  g_Whi[(size_t)IDIM * GDIM];
__device__ __nv_bfloat16  g_Wlo[(size_t)IDIM * GDIM];
__device__ __nv_bfloat16  g_Uhi[(size_t)HDIM * GDIM];
__device__ __nv_bfloat16  g_Ulo[(size_t)HDIM * GDIM];
__device__ __nv_bfloat16  g_hbuf[2][2][BDIM * HDIM];     // [parity][hi/lo]
__device__ unsigned       g_bar;

// ---------------- helpers ----------------
#define MMA_BF16(Cr, Ar, Br)                                                    \
  asm volatile("mma.sync.aligned.m16n8k16.row.col.f32.bf16.bf16.f32 "           \
               "{%0,%1,%2,%3},{%4,%5,%6,%7},{%8,%9},{%0,%1,%2,%3};"             \
               : "+f"(Cr[0]), "+f"(Cr[1]), "+f"(Cr[2]), "+f"(Cr[3])             \
               : "r"(Ar[0]), "r"(Ar[1]), "r"(Ar[2]), "r"(Ar[3]),                \
                 "r"(Br[0]), "r"(Br[1]))

__device__ __forceinline__ float sigm(float x) { return 1.f / (1.f + __expf(-x)); }
__device__ __forceinline__ float tanh_f(float x) {
    float e = __expf(-2.f * fabsf(x));
    float r = (1.f - e) / (1.f + e);
    return (x < 0.f) ? -r : r;
}

// ---------------- prep: fp32 -> bf16 hi/lo split ----------------
__global__ void split_kernel(const float* __restrict__ src, int n, int which) {
    __nv_bfloat16 *hi, *lo;
    if (which == 0)      { hi = g_xhi; lo = g_xlo; }
    else if (which == 1) { hi = g_Whi; lo = g_Wlo; }
    else                 { hi = g_Uhi; lo = g_Ulo; }
    int i = blockIdx.x * blockDim.x + threadIdx.x;
    if (i < n) {
        float v = src[i];
        __nv_bfloat16 h = __float2bfloat16(v);
        hi[i] = h;
        lo[i] = __float2bfloat16(v - __bfloat162float(h));
    }
}

__global__ void zero_state_kernel() {
    int i = blockIdx.x * blockDim.x + threadIdx.x;
    if (i == 0) g_bar = 0;
    if (i < BDIM * HDIM) {
        __nv_bfloat16 z = __float2bfloat16(0.f);
        g_hbuf[0][0][i] = z; g_hbuf[0][1][i] = z;
        g_hbuf[1][0][i] = z; g_hbuf[1][1][i] = z;
    }
}

// ---------------- phase 1: xW = x @ W + bias  (bf16x3 MMA) ----------------
// CTA tile 128x64, 4 warps in 2x2 grid (warp tile 64x32), BK=16, double-buffered.
__global__ __launch_bounds__(128) void gemm_xw_kernel(const float* __restrict__ bias) {
    const int m0 = blockIdx.y * 128;
    const int n0 = blockIdx.x * 64;
    const int tid = threadIdx.x;
    const int warp = tid >> 5, lane = tid & 31;
    const int g = lane >> 2, tig = lane & 3;
    const int wm = warp >> 1, wn = warp & 1;

    __shared__ __align__(16) __nv_bfloat16 As[2][2][128][24];  // [buf][hi/lo][m][k]
    __shared__ __align__(16) __nv_bfloat16 Bs[2][2][64][24];   // [buf][hi/lo][n][k]

    float C[4][4][4];
#pragma unroll
    for (int a = 0; a < 4; a++)
#pragma unroll
        for (int b = 0; b < 4; b++)
#pragma unroll
            for (int c = 0; c < 4; c++) C[a][b][c] = 0.f;

    const int ar = tid >> 2;          // A row  0..31 (+32*it)
    const int ac = (tid & 3) * 4;     // A col  0,4,8,12
    const int bk = tid >> 4;          // B k    0..7 (+8*it)
    const int bc = (tid & 15) * 4;    // B col  0..60

    uint2 regA[2][4];
    uint2 regB[2][2];

    auto gload = [&](int k0) {
#pragma unroll
        for (int it = 0; it < 4; ++it) {
            size_t off = (size_t)(m0 + ar + 32 * it) * IDIM + k0 + ac;
            regA[0][it] = *reinterpret_cast<const uint2*>(g_xhi + off);
            regA[1][it] = *reinterpret_cast<const uint2*>(g_xlo + off);
        }
#pragma unroll
        for (int it = 0; it < 2; ++it) {
            size_t off = (size_t)(k0 + bk + 8 * it) * GDIM + n0 + bc;
            regB[0][it] = *reinterpret_cast<const uint2*>(g_Whi + off);
            regB[1][it] = *reinterpret_cast<const uint2*>(g_Wlo + off);
        }
    };
    auto sts = [&](int buf) {
#pragma unroll
        for (int h = 0; h < 2; ++h)
#pragma unroll
            for (int it = 0; it < 4; ++it)
                *reinterpret_cast<uint2*>(&As[buf][h][ar + 32 * it][ac]) = regA[h][it];
#pragma unroll
        for (int h = 0; h < 2; ++h)
#pragma unroll
            for (int it = 0; it < 2; ++it) {
                __nv_bfloat16 tmp[4];
                *reinterpret_cast<uint2*>(tmp) = regB[h][it];
#pragma unroll
                for (int j = 0; j < 4; ++j) Bs[buf][h][bc + j][bk + 8 * it] = tmp[j];
            }
    };

    gload(0);
    sts(0);
    __syncthreads();

    const int KT = IDIM / 16;
    for (int kt = 0; kt < KT; ++kt) {
        const int cur = kt & 1;
        if (kt + 1 < KT) gload((kt + 1) * 16);

        uint32_t aF[2][4][4];
        uint32_t bF[2][4][2];
#pragma unroll
        for (int mt = 0; mt < 4; ++mt) {
            const int rb = wm * 64 + mt * 16;
#pragma unroll
            for (int h = 0; h < 2; ++h) {
                aF[h][mt][0] = *reinterpret_cast<const uint32_t*>(&As[cur][h][rb + g][2 * tig]);
                aF[h][mt][1] = *reinterpret_cast<const uint32_t*>(&As[cur][h][rb + g + 8][2 * tig]);
                aF[h][mt][2] = *reinterpret_cast<const uint32_t*>(&As[cur][h][rb + g][2 * tig + 8]);
                aF[h][mt][3] = *reinterpret_cast<const uint32_t*>(&As[cur][h][rb + g + 8][2 * tig + 8]);
            }
        }
#pragma unroll
        for (int nt = 0; nt < 4; ++nt) {
            const int nb = wn * 32 + nt * 8;
#pragma unroll
            for (int h = 0; h < 2; ++h) {
                bF[h][nt][0] = *reinterpret_cast<const uint32_t*>(&Bs[cur][h][nb + g][2 * tig]);
                bF[h][nt][1] = *reinterpret_cast<const uint32_t*>(&Bs[cur][h][nb + g][2 * tig + 8]);
            }
        }
#pragma unroll
        for (int mt = 0; mt < 4; ++mt)
#pragma unroll
            for (int nt = 0; nt < 4; ++nt) {
                MMA_BF16(C[mt][nt], aF[0][mt], bF[0][nt]);  // hi*hi
                MMA_BF16(C[mt][nt], aF[0][mt], bF[1][nt]);  // hi*lo
                MMA_BF16(C[mt][nt], aF[1][mt], bF[0][nt]);  // lo*hi
            }

        if (kt + 1 < KT) sts(cur ^ 1);
        __syncthreads();
    }

#pragma unroll
    for (int mt = 0; mt < 4; ++mt) {
        const int row0 = m0 + wm * 64 + mt * 16 + g;
#pragma unroll
        for (int nt = 0; nt < 4; ++nt) {
            const int col = n0 + wn * 32 + nt * 8 + 2 * tig;
            const float b0 = bias[col], b1 = bias[col + 1];
            float2 v;
            v.x = C[mt][nt][0] + b0; v.y = C[mt][nt][1] + b1;
            *reinterpret_cast<float2*>(&g_xW[(size_t)row0 * GDIM + col]) = v;
            v.x = C[mt][nt][2] + b0; v.y = C[mt][nt][3] + b1;
            *reinterpret_cast<float2*>(&g_xW[(size_t)(row0 + 8) * GDIM + col]) = v;
        }
    }
}

// ---------------- phase 2: persistent recurrent kernel ----------------------
// 128 CTAs (all co-resident), 256 threads. Each CTA owns 8 hidden units and
// keeps its U slice (32 gate-cols x 1024 K, hi+lo) resident in SMEM for all
// 512 timesteps. split-K over two warp-groups (warps 0-3: K[0:512],
// warps 4-7: K[512:1024]) with an SMEM reduction. c-state lives in registers.
// h is exchanged through a double-buffered (parity) global buffer with a
// grid-wide sense barrier per step.
//
// SMEM layout (dynamic):
//   Us: [2(hi/lo)][32 n][1032 k]  bf16   = 132096 B   (pad 1032 -> conflict-free)
//   As: [2 buf][2 hi/lo][2 half][64 b][24 k] bf16 = 24576 B  (reused as fp32 red)
#define US_PAD   1032
#define US_BYTES (2 * 32 * US_PAD * 2)
#define AS_BYTES (2 * 2 * 2 * 64 * 24 * 2)
#define SMEM_DYN (US_BYTES + AS_BYTES)

__global__ __launch_bounds__(256) void lstm_persistent_kernel(float* __restrict__ out,
                                                              float* __restrict__ ht,
                                                              float* __restrict__ ct) {
    const int j0 = blockIdx.x * 8;
    const int tid = threadIdx.x;
    const int warp = tid >> 5, lane = tid & 31;
    const int g = lane >> 2, tig = lane & 3;
    const int half = warp >> 2;            // K-half of this warp
    const int wb = warp & 3;               // batch group (rows wb*16..+15)

    extern __shared__ __align__(16) char smem_raw[];
    __nv_bfloat16* Us = reinterpret_cast<__nv_bfloat16*>(smem_raw);
    __nv_bfloat16* As = reinterpret_cast<__nv_bfloat16*>(smem_raw + US_BYTES);
    float* red = reinterpret_cast<float*>(smem_raw + US_BYTES);   // reuse of As

#define USI(hl, n, k)  (((hl) * 32 + (n)) * US_PAD + (k))
#define ASI(buf, hl, hf, r, k) ((((((buf)*2 + (hl))*2 + (hf))*64 + (r))*24) + (k))

    // ---- one-time: load this CTA's U slice into SMEM ----
    // smem col n in [0,32): gate group n>>3, unit j0 + (n&7).
#pragma unroll
    for (int hl = 0; hl < 2; ++hl) {
        const __nv_bfloat16* Ug = hl ? g_Ulo : g_Uhi;
        for (int i = tid; i < 4096; i += 256) {
            int k = i >> 2, grp = i & 3;
            uint4 v = *reinterpret_cast<const uint4*>(Ug + (size_t)k * GDIM + grp * 1024 + j0);
            __nv_bfloat16 tmp[8];
            *reinterpret_cast<uint4*>(tmp) = v;
#pragma unroll
            for (int c = 0; c < 8; ++c) Us[USI(hl, grp * 8 + c, k)] = tmp[c];
        }
    }
    __syncthreads();

    // A-staging loader mapping (256 threads cover 2 halves x 2 hl x 64 rows x 16 k)
    const int ld_half = tid >> 7;
    const int ld_row  = (tid >> 1) & 63;
    const int ld_kq   = tid & 1;

    float creg[4] = {0.f, 0.f, 0.f, 0.f};   // persistent c state (warps 0-3)

    for (int t = 0; t < SDIM; ++t) {
        const int p = t & 1, np = p ^ 1;
        const __nv_bfloat16* __restrict__ hhi = g_hbuf[p][0];
        const __nv_bfloat16* __restrict__ hlo = g_hbuf[p][1];

        // accumulators: warps 0-3 seed from xW (has bias), warps 4-7 zero
        float C[4][4];
        if (warp < 4) {
            const int b0 = warp * 16 + g;
#pragma unroll
            for (int nt = 0; nt < 4; ++nt) {
                const int n = nt * 1024 + j0 + 2 * tig;
                float2 v0 = *reinterpret_cast<const float2*>(&g_xW[(size_t)(b0 * SDIM + t) * GDIM + n]);
                float2 v1 = *reinterpret_cast<const float2*>(&g_xW[(size_t)((b0 + 8) * SDIM + t) * GDIM + n]);
                C[nt][0] = v0.x; C[nt][1] = v0.y; C[nt][2] = v1.x; C[nt][3] = v1.y;
            }
        } else {
#pragma unroll
            for (int nt = 0; nt < 4; ++nt)
#pragma unroll
                for (int c = 0; c < 4; ++c) C[nt][c] = 0.f;
        }

        uint4 regA[2];
        auto gload = [&](int it) {
            const int k0 = ld_half * 512 + it * 16 + ld_kq * 8;
            regA[0] = *reinterpret_cast<const uint4*>(hhi + ld_row * HDIM + k0);
            regA[1] = *reinterpret_cast<const uint4*>(hlo + ld_row * HDIM + k0);
        };
        auto sts = [&](int buf) {
#pragma unroll
            for (int hl = 0; hl < 2; ++hl)
                *reinterpret_cast<uint4*>(&As[ASI(buf, hl, ld_half, ld_row, ld_kq * 8)]) = regA[hl];
        };

        gload(0);
        sts(0);
        __syncthreads();

        const int KT = 32;   // 512 K per half / 16
        for (int kt = 0; kt < KT; ++kt) {
            const int cur = kt & 1;
            if (kt + 1 < KT) gload(kt + 1);

            const int kk = half * 512 + kt * 16;
            uint32_t aF[2][4];
            uint32_t bF[2][4][2];
            const int rb = wb * 16;
#pragma unroll
            for (int hl = 0; hl < 2; ++hl) {
                aF[hl][0] = *reinterpret_cast<const uint32_t*>(&As[ASI(cur, hl, half, rb + g, 2 * tig)]);
                aF[hl][1] = *reinterpret_cast<const uint32_t*>(&As[ASI(cur, hl, half, rb + g + 8, 2 * tig)]);
                aF[hl][2] = *reinterpret_cast<const uint32_t*>(&As[ASI(cur, hl, half, rb + g, 2 * tig + 8)]);
                aF[hl][3] = *reinterpret_cast<const uint32_t*>(&As[ASI(cur, hl, half, rb + g + 8, 2 * tig + 8)]);
            }
#pragma unroll
            for (int nt = 0; nt < 4; ++nt)
#pragma unroll
                for (int hl = 0; hl < 2; ++hl) {
                    bF[hl][nt][0] = *reinterpret_cast<const uint32_t*>(&Us[USI(hl, nt * 8 + g, kk + 2 * tig)]);
                    bF[hl][nt][1] = *reinterpret_cast<const uint32_t*>(&Us[USI(hl, nt * 8 + g, kk + 2 * tig + 8)]);
                }
#pragma unroll
            for (int nt = 0; nt < 4; ++nt) {
                MMA_BF16(C[nt], aF[0], bF[0][nt]);
                MMA_BF16(C[nt], aF[0], bF[1][nt]);
                MMA_BF16(C[nt], aF[1], bF[0][nt]);
            }

            if (kt + 1 < KT) sts(cur ^ 1);
            __syncthreads();
        }

        // ---- split-K reduction: warps 4-7 dump partials, warps 0-3 add ----
        if (warp >= 4) {
            float* dst = &red[((warp - 4) * 32 + lane) * 16];
#pragma unroll
            for (int nt = 0; nt < 4; ++nt)
#pragma unroll
                for (int c = 0; c < 4; ++c) dst[nt * 4 + c] = C[nt][c];
        }
        __syncthreads();

        if (warp < 4) {
            const float* src = &red[(warp * 32 + lane) * 16];
#pragma unroll
            for (int nt = 0; nt < 4; ++nt)
#pragma unroll
                for (int c = 0; c < 4; ++c) C[nt][c] += src[nt * 4 + c];

            // ---- fused LSTM cell epilogue ----
#pragma unroll
            for (int ci = 0; ci < 4; ++ci) {
                const int b = warp * 16 + g + ((ci & 2) ? 8 : 0);
                const int j = j0 + 2 * tig + (ci & 1);
                const float is = sigm(C[0][ci]);
                const float fs = sigm(C[1][ci]);
                const float gt = tanh_f(C[2][ci]);
                const float os = sigm(C[3][ci]);
                const float cnew = fs * creg[ci] + is * gt;
                creg[ci] = cnew;
                const float h = os * tanh_f(cnew);
                out[(size_t)(b * SDIM + t) * HDIM + j] = h;
                __nv_bfloat16 hh = __float2bfloat16(h);
                g_hbuf[np][0][b * HDIM + j] = hh;
                g_hbuf[np][1][b * HDIM + j] = __float2bfloat16(h - __bfloat162float(hh));
                if (ht != nullptr && t == SDIM - 1) {
                    ht[b * HDIM + j] = h;
                    ct[b * HDIM + j] = cnew;
                }
            }
        }

        // ---- grid-wide barrier (publish h[np], retire reads of h[p]) ----
        __threadfence();
        __syncthreads();
        if (tid == 0) {
            atomicAdd(&g_bar, 1u);
            const unsigned target = (unsigned)(t + 1) * (unsigned)NCTA;
            while (*(volatile unsigned*)&g_bar < target) { }
            __threadfence();
        }
        __syncthreads();
    }
}

// ---------------- launch ----------------
extern "C" void kernel_launch(void* const* d_in, const int* in_sizes, int n_in,
                              void* d_out, int out_size) {
    const float* x    = (const float*)d_in[0];
    const float* W    = (const float*)d_in[1];
    const float* U    = (const float*)d_in[2];
    const float* bias = (const float*)d_in[3];
    float* out = (float*)d_out;
    (void)in_sizes; (void)n_in;

    static int smem_set = 0;
    if (!smem_set) {
        cudaFuncSetAttribute(lstm_persistent_kernel,
                             cudaFuncAttributeMaxDynamicSharedMemorySize, SMEM_DYN);
        smem_set = 1;
    }

    {
        int n = MROWS * IDIM;
        split_kernel<<<(n + 255) / 256, 256>>>(x, n, 0);
    }
    {
        int n = IDIM * GDIM;
        split_kernel<<<(n + 255) / 256, 256>>>(W, n, 1);
        split_kernel<<<(n + 255) / 256, 256>>>(U, n, 2);
    }
    zero_state_kernel<<<(BDIM * HDIM + 255) / 256, 256>>>();

    gemm_xw_kernel<<<dim3(GDIM / 64, MROWS / 128), 128>>>(bias);

    float* ht = nullptr;
    float* ct = nullptr;
    long long hs_elems = (long long)BDIM * SDIM * HDIM;
    if ((long long)out_size >= hs_elems + 2LL * BDIM * HDIM) {
        ht = out + hs_elems;
        ct = ht + (long long)BDIM * HDIM;
    }

    lstm_persistent_kernel<<<NCTA, 256, SMEM_DYN>>>(out, ht, ct);
}